// round 7
// baseline (speedup 1.0000x reference)
#include <cuda_runtime.h>
#include <cstdint>

#define NN 50000
#define NE 800000

// ---------------- device scratch ----------------
__device__ float g_nm[(size_t)NN * 128];   // [n][0:64]=x@W1a+b1, [n][64:128]=x@W1b
__device__ float g_hsum[(size_t)NN * 64];  // per-node sum of relu(h)
__device__ int   g_cnt[NN];                // in-degree (histogram)
__device__ int   g_start[NN];              // CSR start (unused after bin, kept for clarity)
__device__ int   g_cursor[NN];             // binning cursors
__device__ int   g_bsum[256];              // per-block sums for scan
__device__ int   g_boff[256];              // per-block offsets
__device__ int   g_ssrc[NE];               // sorted-by-dst: src
__device__ int   g_sdst[NE];               // sorted-by-dst: dst
__device__ int   g_seid[NE];               // sorted-by-dst: original edge id

// ---------------- helpers ----------------
__device__ __forceinline__ uint32_t f2tf32(float f) {
    uint32_t r;
    asm("cvt.rna.tf32.f32 %0, %1;" : "=r"(r) : "f"(f));
    return r;
}
__device__ __forceinline__ void mma_tf32(float c[4],
                                         uint32_t a0, uint32_t a1, uint32_t a2, uint32_t a3,
                                         uint32_t b0, uint32_t b1) {
    asm volatile(
        "mma.sync.aligned.m16n8k8.row.col.f32.tf32.tf32.f32 "
        "{%0,%1,%2,%3}, {%4,%5,%6,%7}, {%8,%9}, {%0,%1,%2,%3};"
        : "+f"(c[0]), "+f"(c[1]), "+f"(c[2]), "+f"(c[3])
        : "r"(a0), "r"(a1), "r"(a2), "r"(a3), "r"(b0), "r"(b1));
}
__device__ __forceinline__ void red_add_v4(float* p, float a, float b, float c, float d) {
    asm volatile("red.global.add.v4.f32 [%0], {%1, %2, %3, %4};"
        :: "l"(p), "f"(a), "f"(b), "f"(c), "f"(d) : "memory");
}

// ================= zero: g_hsum + g_cnt =================
__global__ void zero_kernel(int M) {
    int i = blockIdx.x * blockDim.x + threadIdx.x;
    int h4 = M * 16;                       // float4 count of g_hsum
    if (i < h4) reinterpret_cast<float4*>(g_hsum)[i] = make_float4(0.f, 0.f, 0.f, 0.f);
    else if (i < h4 + M) g_cnt[i - h4] = 0;
}

// ================= hist: in-degree =================
__global__ void hist_kernel(const int* __restrict__ ei, int E) {
    int e = blockIdx.x * blockDim.x + threadIdx.x;
    if (e < E) atomicAdd(&g_cnt[ei[E + e]], 1);
}

// ================= scan (3 stages, blocks of 256) =================
__global__ void scan1_kernel(int M) {
    __shared__ int s[256];
    int t = threadIdx.x, i = blockIdx.x * 256 + t;
    s[t] = (i < M) ? g_cnt[i] : 0;
    __syncthreads();
    for (int off = 128; off > 0; off >>= 1) {
        if (t < off) s[t] += s[t + off];
        __syncthreads();
    }
    if (t == 0) g_bsum[blockIdx.x] = s[0];
}
__global__ void scan2_kernel(int nb) {
    __shared__ int s[256];
    int t = threadIdx.x;
    int v = (t < nb) ? g_bsum[t] : 0;
    s[t] = v;
    __syncthreads();
    for (int off = 1; off < 256; off <<= 1) {
        int u = (t >= off) ? s[t - off] : 0;
        __syncthreads();
        s[t] += u;
        __syncthreads();
    }
    if (t < nb) g_boff[t] = s[t] - v;      // exclusive
}
__global__ void scan3_kernel(int M) {
    __shared__ int s[256];
    int t = threadIdx.x, i = blockIdx.x * 256 + t;
    int v = (i < M) ? g_cnt[i] : 0;
    s[t] = v;
    __syncthreads();
    for (int off = 1; off < 256; off <<= 1) {
        int u = (t >= off) ? s[t - off] : 0;
        __syncthreads();
        s[t] += u;
        __syncthreads();
    }
    if (i < M) {
        int st = s[t] - v + g_boff[blockIdx.x];   // exclusive + block offset
        g_start[i] = st;
        g_cursor[i] = st;
    }
}

// ================= bin: scatter edges into dst-sorted order =================
__global__ void bin_kernel(const int* __restrict__ ei, int E) {
    int e = blockIdx.x * blockDim.x + threadIdx.x;
    if (e < E) {
        int src = ei[e], dst = ei[E + e];
        int pos = atomicAdd(&g_cursor[dst], 1);
        g_ssrc[pos] = src;
        g_sdst[pos] = dst;
        g_seid[pos] = e;
    }
}

// ================= K1: g_nm = x @ [W1a|W1b] (+b1 first half), A destaged =================
__global__ __launch_bounds__(256)
void k1_kernel(const float* __restrict__ x, const float* __restrict__ W1,
               const float* __restrict__ b1, int M) {
    __shared__ uint32_t Ws[64 * 136];
    const int tid = threadIdx.x, lane = tid & 31, wid = tid >> 5;
    const int g = lane >> 2, tg = lane & 3;
    const int m0 = blockIdx.x * 128;

    for (int idx = tid; idx < 64 * 128; idx += 256) {
        int k = idx >> 7, n = idx & 127;
        float w = (n < 64) ? W1[k * 64 + n] : W1[(64 + k) * 64 + (n - 64)];
        Ws[k * 136 + n] = f2tf32(w);
    }
    __syncthreads();

    const int rb = wid * 16;
    const int r0 = m0 + rb + g, r1 = r0 + 8;
    const float* xr0 = x + (size_t)(r0 < M ? r0 : M - 1) * 64;
    const float* xr1 = x + (size_t)(r1 < M ? r1 : M - 1) * 64;

    float acc[16][4];
    #pragma unroll
    for (int nt = 0; nt < 16; nt++) acc[nt][0] = acc[nt][1] = acc[nt][2] = acc[nt][3] = 0.f;

    #pragma unroll
    for (int kt = 0; kt < 8; kt++) {
        const int k0 = kt * 8;
        uint32_t a0 = f2tf32(__ldg(xr0 + k0 + tg));
        uint32_t a1 = f2tf32(__ldg(xr1 + k0 + tg));
        uint32_t a2 = f2tf32(__ldg(xr0 + k0 + tg + 4));
        uint32_t a3 = f2tf32(__ldg(xr1 + k0 + tg + 4));
        #pragma unroll
        for (int nt = 0; nt < 16; nt++) {
            uint32_t b0 = Ws[(k0 + tg) * 136 + 8 * nt + g];
            uint32_t b1v = Ws[(k0 + tg + 4) * 136 + 8 * nt + g];
            mma_tf32(acc[nt], a0, a1, a2, a3, b0, b1v);
        }
    }
    #pragma unroll
    for (int nt = 0; nt < 16; nt++) {
        const int col = 8 * nt + 2 * tg;
        float e0 = 0.f, e1 = 0.f;
        if (col < 64) { e0 = __ldg(b1 + col); e1 = __ldg(b1 + col + 1); }
        if (r0 < M) *reinterpret_cast<float2*>(g_nm + (size_t)r0 * 128 + col)
                        = make_float2(acc[nt][0] + e0, acc[nt][1] + e1);
        if (r1 < M) *reinterpret_cast<float2*>(g_nm + (size_t)r1 * 128 + col)
                        = make_float2(acc[nt][2] + e0, acc[nt][3] + e1);
    }
}

// ================= MSG: sorted edges -> h = relu(pre+post+ea@W1e) -> segmented reduce =================
// smem words: Aea[128*20] | Wes[16*136] | Acc[128*68] | Ssrc[128] | Sdst[128]
#define AEA_O  0
#define WES_O  (128 * 20)
#define ACC_O  (WES_O + 16 * 136)
#define SSRC_O (ACC_O + 128 * 68)
#define SDST_O (SSRC_O + 128)
#define MSG_SMEM ((SDST_O + 128) * 4)
__global__ __launch_bounds__(256)
void msg_kernel(const float* __restrict__ ea, const float* __restrict__ W1, int E) {
    extern __shared__ float sm[];
    uint32_t* Aea = reinterpret_cast<uint32_t*>(sm) + AEA_O;
    uint32_t* Wes = reinterpret_cast<uint32_t*>(sm) + WES_O;
    float*    Acc = sm + ACC_O;
    int*      Ssrc = reinterpret_cast<int*>(sm) + SSRC_O;
    int*      Sdst = reinterpret_cast<int*>(sm) + SDST_O;

    const int tid = threadIdx.x, lane = tid & 31, wid = tid >> 5;
    const int g = lane >> 2, tg = lane & 3;
    const int base = blockIdx.x * 128;

    if (tid < 128) {
        int p = base + tid;
        Ssrc[tid] = (p < E) ? g_ssrc[p] : 0;
        Sdst[tid] = (p < E) ? g_sdst[p] : -1;
    }
    // gather ea rows by sorted edge id (tf32)
    #pragma unroll
    for (int pp = 0; pp < 2; pp++) {
        int q = tid + 256 * pp;           // 0..511
        int r = q >> 2, c = (q & 3) * 4;
        int p = base + r;
        float4 v = make_float4(0.f, 0.f, 0.f, 0.f);
        if (p < E) {
            int eid = __ldg(g_seid + p);
            v = __ldg(reinterpret_cast<const float4*>(ea + (size_t)eid * 16 + c));
        }
        uint4 u; u.x = f2tf32(v.x); u.y = f2tf32(v.y); u.z = f2tf32(v.z); u.w = f2tf32(v.w);
        *reinterpret_cast<uint4*>(Aea + r * 20 + c) = u;
    }
    for (int idx = tid; idx < 16 * 64; idx += 256) {
        int k = idx >> 6, n = idx & 63;
        Wes[k * 136 + n] = f2tf32(W1[(128 + k) * 64 + n]);
    }
    __syncthreads();

    // tiny MMA: ea[128x16] @ W1e[16x64]
    const int rb = wid * 16;
    float acc[8][4];
    #pragma unroll
    for (int nt = 0; nt < 8; nt++) acc[nt][0] = acc[nt][1] = acc[nt][2] = acc[nt][3] = 0.f;
    #pragma unroll
    for (int kt = 0; kt < 2; kt++) {
        const int k0 = kt * 8;
        uint32_t a0 = Aea[(rb + g) * 20 + k0 + tg];
        uint32_t a1 = Aea[(rb + g + 8) * 20 + k0 + tg];
        uint32_t a2 = Aea[(rb + g) * 20 + k0 + tg + 4];
        uint32_t a3 = Aea[(rb + g + 8) * 20 + k0 + tg + 4];
        #pragma unroll
        for (int nt = 0; nt < 8; nt++) {
            uint32_t b0 = Wes[(k0 + tg) * 136 + 8 * nt + g];
            uint32_t b1v = Wes[(k0 + tg + 4) * 136 + 8 * nt + g];
            mma_tf32(acc[nt], a0, a1, a2, a3, b0, b1v);
        }
    }
    #pragma unroll
    for (int nt = 0; nt < 8; nt++) {
        const int col = 8 * nt + 2 * tg;
        *reinterpret_cast<float2*>(Acc + (rb + g) * 68 + col)     = make_float2(acc[nt][0], acc[nt][1]);
        *reinterpret_cast<float2*>(Acc + (rb + g + 8) * 68 + col) = make_float2(acc[nt][2], acc[nt][3]);
    }
    __syncthreads();

    // pass 2: h = relu(pre[src] + post[dst] + acc) back into Acc
    const int rr = tid >> 4;              // 0..15
    const int c4 = (tid & 15) * 4;        // col quad
    #pragma unroll
    for (int p = 0; p < 8; p++) {
        const int r = p * 16 + rr;
        if (base + r < E) {
            const int src = Ssrc[r], dst = Sdst[r];
            float4 pre  = __ldg(reinterpret_cast<const float4*>(g_nm + (size_t)src * 128 + c4));
            float4 post = __ldg(reinterpret_cast<const float4*>(g_nm + (size_t)dst * 128 + 64 + c4));
            float4 a = *reinterpret_cast<const float4*>(Acc + r * 68 + c4);
            a.x = fmaxf(pre.x + post.x + a.x, 0.f);
            a.y = fmaxf(pre.y + post.y + a.y, 0.f);
            a.z = fmaxf(pre.z + post.z + a.z, 0.f);
            a.w = fmaxf(pre.w + post.w + a.w, 0.f);
            *reinterpret_cast<float4*>(Acc + r * 68 + c4) = a;
        }
    }
    __syncthreads();

    // pass 3: segmented reduce — run leaders sum their run and issue one red.v4
    #pragma unroll
    for (int p = 0; p < 8; p++) {
        const int r = p * 16 + rr;
        const int d = Sdst[r];
        if (d >= 0 && (r == 0 || Sdst[r - 1] != d)) {
            float4 s = *reinterpret_cast<const float4*>(Acc + r * 68 + c4);
            int rn = r + 1;
            while (rn < 128 && Sdst[rn] == d) {
                float4 v = *reinterpret_cast<const float4*>(Acc + rn * 68 + c4);
                s.x += v.x; s.y += v.y; s.z += v.z; s.w += v.w;
                rn++;
            }
            red_add_v4(g_hsum + (size_t)d * 64 + c4, s.x, s.y, s.z, s.w);
        }
    }
}

// ================= K3: out = g_hsum @ W2 + deg (x) b2, A destaged =================
__global__ __launch_bounds__(256)
void k3_kernel(const float* __restrict__ W2, const float* __restrict__ b2,
               float* __restrict__ out, int M) {
    __shared__ uint32_t Ws[64 * 72];
    const int tid = threadIdx.x, lane = tid & 31, wid = tid >> 5;
    const int g = lane >> 2, tg = lane & 3;
    const int m0 = blockIdx.x * 128;

    for (int idx = tid; idx < 64 * 64; idx += 256) {
        int k = idx >> 6, n = idx & 63;
        Ws[k * 72 + n] = f2tf32(W2[idx]);
    }
    __syncthreads();

    const int rb = wid * 16;
    const int r0 = m0 + rb + g, r1 = r0 + 8;
    const float* h0 = g_hsum + (size_t)(r0 < M ? r0 : M - 1) * 64;
    const float* h1 = g_hsum + (size_t)(r1 < M ? r1 : M - 1) * 64;

    float acc[8][4];
    #pragma unroll
    for (int nt = 0; nt < 8; nt++) acc[nt][0] = acc[nt][1] = acc[nt][2] = acc[nt][3] = 0.f;

    #pragma unroll
    for (int kt = 0; kt < 8; kt++) {
        const int k0 = kt * 8;
        uint32_t a0 = f2tf32(__ldg(h0 + k0 + tg));
        uint32_t a1 = f2tf32(__ldg(h1 + k0 + tg));
        uint32_t a2 = f2tf32(__ldg(h0 + k0 + tg + 4));
        uint32_t a3 = f2tf32(__ldg(h1 + k0 + tg + 4));
        #pragma unroll
        for (int nt = 0; nt < 8; nt++) {
            uint32_t b0 = Ws[(k0 + tg) * 72 + 8 * nt + g];
            uint32_t b1v = Ws[(k0 + tg + 4) * 72 + 8 * nt + g];
            mma_tf32(acc[nt], a0, a1, a2, a3, b0, b1v);
        }
    }
    const float d0 = (r0 < M) ? (float)g_cnt[r0] : 0.f;
    const float d1 = (r1 < M) ? (float)g_cnt[r1] : 0.f;
    #pragma unroll
    for (int nt = 0; nt < 8; nt++) {
        const int col = 8 * nt + 2 * tg;
        const float bb0 = __ldg(b2 + col), bb1 = __ldg(b2 + col + 1);
        if (r0 < M) *reinterpret_cast<float2*>(out + (size_t)r0 * 64 + col)
                        = make_float2(acc[nt][0] + d0 * bb0, acc[nt][1] + d0 * bb1);
        if (r1 < M) *reinterpret_cast<float2*>(out + (size_t)r1 * 64 + col)
                        = make_float2(acc[nt][2] + d1 * bb0, acc[nt][3] + d1 * bb1);
    }
}

// ---------------- launch ----------------
extern "C" void kernel_launch(void* const* d_in, const int* in_sizes, int n_in,
                              void* d_out, int out_size) {
    const float* x  = (const float*)d_in[0];
    const int*   ei = (const int*)d_in[1];      // int32 (JAX x64 disabled)
    const float* ea = (const float*)d_in[2];
    const float* W1 = (const float*)d_in[3];
    const float* b1 = (const float*)d_in[4];
    const float* W2 = (const float*)d_in[5];
    const float* b2 = (const float*)d_in[6];
    float* out = (float*)d_out;

    int E = in_sizes[1] / 2;
    int M = out_size / 64;
    int mtiles = (M + 127) / 128;
    int etiles = (E + 127) / 128;
    int nb = (M + 255) / 256;                    // scan blocks (<=256)

    cudaFuncSetAttribute(msg_kernel, cudaFuncAttributeMaxDynamicSharedMemorySize, MSG_SMEM);

    int zn = M * 16 + M;
    zero_kernel<<<(zn + 255) / 256, 256>>>(M);
    hist_kernel<<<(E + 255) / 256, 256>>>(ei, E);
    k1_kernel<<<mtiles, 256>>>(x, W1, b1, M);
    scan1_kernel<<<nb, 256>>>(M);
    scan2_kernel<<<1, 256>>>(nb);
    scan3_kernel<<<nb, 256>>>(M);
    bin_kernel<<<(E + 255) / 256, 256>>>(ei, E);
    msg_kernel<<<etiles, 256, MSG_SMEM>>>(ea, W1, E);
    k3_kernel<<<mtiles, 256>>>(W2, b2, out, M);
}

// round 8
// speedup vs baseline: 1.5900x; 1.5900x over previous
#include <cuda_runtime.h>
#include <cstdint>

#define NN 50000
#define NE 800000

// ---------------- device scratch ----------------
__device__ float g_nm[(size_t)NN * 128];   // [n][0:64]=x@W1a+b1, [n][64:128]=x@W1b
__device__ float g_hsum[(size_t)NN * 64];  // per-node sum of relu(h)
__device__ float g_deg[NN];                // per-node edge count

// ---------------- helpers ----------------
__device__ __forceinline__ uint32_t f2tf32(float f) {
    uint32_t r;
    asm("cvt.rna.tf32.f32 %0, %1;" : "=r"(r) : "f"(f));
    return r;
}
__device__ __forceinline__ void mma_tf32(float c[4],
                                         uint32_t a0, uint32_t a1, uint32_t a2, uint32_t a3,
                                         uint32_t b0, uint32_t b1) {
    asm volatile(
        "mma.sync.aligned.m16n8k8.row.col.f32.tf32.tf32.f32 "
        "{%0,%1,%2,%3}, {%4,%5,%6,%7}, {%8,%9}, {%0,%1,%2,%3};"
        : "+f"(c[0]), "+f"(c[1]), "+f"(c[2]), "+f"(c[3])
        : "r"(a0), "r"(a1), "r"(a2), "r"(a3), "r"(b0), "r"(b1));
}
__device__ __forceinline__ void red_add_v4(float* p, float a, float b, float c, float d) {
    asm volatile("red.global.add.v4.f32 [%0], {%1, %2, %3, %4};"
        :: "l"(p), "f"(a), "f"(b), "f"(c), "f"(d) : "memory");
}
__device__ __forceinline__ void red_add_f32(float* p, float v) {
    asm volatile("red.global.add.f32 [%0], %1;" :: "l"(p), "f"(v) : "memory");
}

// ================= zero: g_hsum + g_deg =================
__global__ void zero_kernel(int M) {
    int i = blockIdx.x * blockDim.x + threadIdx.x;
    int h4 = M * 16;
    if (i < h4) reinterpret_cast<float4*>(g_hsum)[i] = make_float4(0.f, 0.f, 0.f, 0.f);
    else if (i < h4 + M) g_deg[i - h4] = 0.f;
}

// ================= K1: g_nm = x @ [W1a|W1b] (+b1 first half), A destaged =================
__global__ __launch_bounds__(256)
void k1_kernel(const float* __restrict__ x, const float* __restrict__ W1,
               const float* __restrict__ b1, int M) {
    __shared__ uint32_t Ws[64 * 136];
    const int tid = threadIdx.x, lane = tid & 31, wid = tid >> 5;
    const int g = lane >> 2, tg = lane & 3;
    const int m0 = blockIdx.x * 128;

    for (int idx = tid; idx < 64 * 128; idx += 256) {
        int k = idx >> 7, n = idx & 127;
        float w = (n < 64) ? W1[k * 64 + n] : W1[(64 + k) * 64 + (n - 64)];
        Ws[k * 136 + n] = f2tf32(w);
    }
    __syncthreads();

    const int rb = wid * 16;
    const int r0 = m0 + rb + g, r1 = r0 + 8;
    const float* xr0 = x + (size_t)(r0 < M ? r0 : M - 1) * 64;
    const float* xr1 = x + (size_t)(r1 < M ? r1 : M - 1) * 64;

    // preload all A fragments (batched LDGs)
    uint32_t afr[8][4];
    #pragma unroll
    for (int kt = 0; kt < 8; kt++) {
        const int k0 = kt * 8;
        afr[kt][0] = f2tf32(__ldg(xr0 + k0 + tg));
        afr[kt][1] = f2tf32(__ldg(xr1 + k0 + tg));
        afr[kt][2] = f2tf32(__ldg(xr0 + k0 + tg + 4));
        afr[kt][3] = f2tf32(__ldg(xr1 + k0 + tg + 4));
    }

    float acc[16][4];
    #pragma unroll
    for (int nt = 0; nt < 16; nt++) acc[nt][0] = acc[nt][1] = acc[nt][2] = acc[nt][3] = 0.f;

    #pragma unroll
    for (int kt = 0; kt < 8; kt++) {
        const int k0 = kt * 8;
        #pragma unroll
        for (int nt = 0; nt < 16; nt++) {
            uint32_t b0 = Ws[(k0 + tg) * 136 + 8 * nt + g];
            uint32_t b1v = Ws[(k0 + tg + 4) * 136 + 8 * nt + g];
            mma_tf32(acc[nt], afr[kt][0], afr[kt][1], afr[kt][2], afr[kt][3], b0, b1v);
        }
    }
    #pragma unroll
    for (int nt = 0; nt < 16; nt++) {
        const int col = 8 * nt + 2 * tg;
        float e0 = 0.f, e1 = 0.f;
        if (col < 64) { e0 = __ldg(b1 + col); e1 = __ldg(b1 + col + 1); }
        if (r0 < M) *reinterpret_cast<float2*>(g_nm + (size_t)r0 * 128 + col)
                        = make_float2(acc[nt][0] + e0, acc[nt][1] + e1);
        if (r1 < M) *reinterpret_cast<float2*>(g_nm + (size_t)r1 * 128 + col)
                        = make_float2(acc[nt][2] + e0, acc[nt][3] + e1);
    }
}

// ================= K2: per-edge h = relu(pre[src]+post[dst]+ea@W1e) -> scatter =================
// smem words: Aea[128*20] | Wes[16*136] | Acc[128*68] | Ssrc[128] | Sdst[128]
#define AEA_O  0
#define WES_O  (128 * 20)
#define ACC_O  (WES_O + 16 * 136)
#define SSRC_O (ACC_O + 128 * 68)
#define SDST_O (SSRC_O + 128)
#define K2_SMEM ((SDST_O + 128) * 4)   // 54784 B
__global__ __launch_bounds__(256)
void k2_kernel(const int* __restrict__ ei, const float* __restrict__ ea,
               const float* __restrict__ W1, int E) {
    extern __shared__ float sm[];
    uint32_t* Aea = reinterpret_cast<uint32_t*>(sm) + AEA_O;
    uint32_t* Wes = reinterpret_cast<uint32_t*>(sm) + WES_O;
    float*    Acc = sm + ACC_O;
    int*      Ssrc = reinterpret_cast<int*>(sm) + SSRC_O;
    int*      Sdst = reinterpret_cast<int*>(sm) + SDST_O;

    const int tid = threadIdx.x, lane = tid & 31, wid = tid >> 5;
    const int g = lane >> 2, tg = lane & 3;
    const int e0 = blockIdx.x * 128;

    if (tid < 128) {
        int e = e0 + tid;
        Ssrc[tid] = (e < E) ? ei[e] : 0;
        Sdst[tid] = (e < E) ? ei[E + e] : 0;
    }
    #pragma unroll
    for (int p = 0; p < 2; p++) {
        int q = tid + 256 * p;            // 0..511
        int r = q >> 2, c = (q & 3) * 4;
        int e = e0 + r;
        float4 v = (e < E) ? __ldg(reinterpret_cast<const float4*>(ea + (size_t)e * 16 + c))
                           : make_float4(0.f, 0.f, 0.f, 0.f);
        uint4 u; u.x = f2tf32(v.x); u.y = f2tf32(v.y); u.z = f2tf32(v.z); u.w = f2tf32(v.w);
        *reinterpret_cast<uint4*>(Aea + r * 20 + c) = u;
    }
    for (int idx = tid; idx < 16 * 64; idx += 256) {
        int k = idx >> 6, n = idx & 63;
        Wes[k * 136 + n] = f2tf32(W1[(128 + k) * 64 + n]);
    }
    __syncthreads();

    // tiny MMA: acc = ea[128x16] @ W1e[16x64]
    const int rb = wid * 16;
    float acc[8][4];
    #pragma unroll
    for (int nt = 0; nt < 8; nt++) acc[nt][0] = acc[nt][1] = acc[nt][2] = acc[nt][3] = 0.f;
    #pragma unroll
    for (int kt = 0; kt < 2; kt++) {
        const int k0 = kt * 8;
        uint32_t a0 = Aea[(rb + g) * 20 + k0 + tg];
        uint32_t a1 = Aea[(rb + g + 8) * 20 + k0 + tg];
        uint32_t a2 = Aea[(rb + g) * 20 + k0 + tg + 4];
        uint32_t a3 = Aea[(rb + g + 8) * 20 + k0 + tg + 4];
        #pragma unroll
        for (int nt = 0; nt < 8; nt++) {
            uint32_t b0 = Wes[(k0 + tg) * 136 + 8 * nt + g];
            uint32_t b1v = Wes[(k0 + tg + 4) * 136 + 8 * nt + g];
            mma_tf32(acc[nt], a0, a1, a2, a3, b0, b1v);
        }
    }
    #pragma unroll
    for (int nt = 0; nt < 8; nt++) {
        const int col = 8 * nt + 2 * tg;
        *reinterpret_cast<float2*>(Acc + (rb + g) * 68 + col)     = make_float2(acc[nt][0], acc[nt][1]);
        *reinterpret_cast<float2*>(Acc + (rb + g + 8) * 68 + col) = make_float2(acc[nt][2], acc[nt][3]);
    }
    __syncthreads();

    // pass 2: batched gather (MLP=16) + relu + scatter
    const int rr = tid >> 4;              // 0..15
    const int c4 = (tid & 15) * 4;        // col quad

    int srcs[8], dsts[8];
    #pragma unroll
    for (int p = 0; p < 8; p++) {
        const int r = p * 16 + rr;
        srcs[p] = Ssrc[r];                // clamped to 0 when invalid
        dsts[p] = Sdst[r];
    }
    float4 pre[8], post[8];
    #pragma unroll
    for (int p = 0; p < 8; p++)
        pre[p]  = __ldg(reinterpret_cast<const float4*>(g_nm + (size_t)srcs[p] * 128 + c4));
    #pragma unroll
    for (int p = 0; p < 8; p++)
        post[p] = __ldg(reinterpret_cast<const float4*>(g_nm + (size_t)dsts[p] * 128 + 64 + c4));

    #pragma unroll
    for (int p = 0; p < 8; p++) {
        const int r = p * 16 + rr;
        if (e0 + r < E) {
            float4 a = *reinterpret_cast<const float4*>(Acc + r * 68 + c4);
            float hx = fmaxf(pre[p].x + post[p].x + a.x, 0.f);
            float hy = fmaxf(pre[p].y + post[p].y + a.y, 0.f);
            float hz = fmaxf(pre[p].z + post[p].z + a.z, 0.f);
            float hw = fmaxf(pre[p].w + post[p].w + a.w, 0.f);
            red_add_v4(g_hsum + (size_t)dsts[p] * 64 + c4, hx, hy, hz, hw);
            if ((tid & 15) == 0) red_add_f32(g_deg + dsts[p], 1.0f);
        }
    }
}

// ================= K3: out = g_hsum @ W2 + deg (x) b2, A destaged =================
__global__ __launch_bounds__(256)
void k3_kernel(const float* __restrict__ W2, const float* __restrict__ b2,
               float* __restrict__ out, int M) {
    __shared__ uint32_t Ws[64 * 72];
    const int tid = threadIdx.x, lane = tid & 31, wid = tid >> 5;
    const int g = lane >> 2, tg = lane & 3;
    const int m0 = blockIdx.x * 128;

    for (int idx = tid; idx < 64 * 64; idx += 256) {
        int k = idx >> 6, n = idx & 63;
        Ws[k * 72 + n] = f2tf32(W2[idx]);
    }
    __syncthreads();

    const int rb = wid * 16;
    const int r0 = m0 + rb + g, r1 = r0 + 8;
    const float* h0 = g_hsum + (size_t)(r0 < M ? r0 : M - 1) * 64;
    const float* h1 = g_hsum + (size_t)(r1 < M ? r1 : M - 1) * 64;

    uint32_t afr[8][4];
    #pragma unroll
    for (int kt = 0; kt < 8; kt++) {
        const int k0 = kt * 8;
        afr[kt][0] = f2tf32(__ldg(h0 + k0 + tg));
        afr[kt][1] = f2tf32(__ldg(h1 + k0 + tg));
        afr[kt][2] = f2tf32(__ldg(h0 + k0 + tg + 4));
        afr[kt][3] = f2tf32(__ldg(h1 + k0 + tg + 4));
    }

    float acc[8][4];
    #pragma unroll
    for (int nt = 0; nt < 8; nt++) acc[nt][0] = acc[nt][1] = acc[nt][2] = acc[nt][3] = 0.f;

    #pragma unroll
    for (int kt = 0; kt < 8; kt++) {
        const int k0 = kt * 8;
        #pragma unroll
        for (int nt = 0; nt < 8; nt++) {
            uint32_t b0 = Ws[(k0 + tg) * 72 + 8 * nt + g];
            uint32_t b1v = Ws[(k0 + tg + 4) * 72 + 8 * nt + g];
            mma_tf32(acc[nt], afr[kt][0], afr[kt][1], afr[kt][2], afr[kt][3], b0, b1v);
        }
    }
    const float d0 = (r0 < M) ? g_deg[r0] : 0.f;
    const float d1 = (r1 < M) ? g_deg[r1] : 0.f;
    #pragma unroll
    for (int nt = 0; nt < 8; nt++) {
        const int col = 8 * nt + 2 * tg;
        const float bb0 = __ldg(b2 + col), bb1 = __ldg(b2 + col + 1);
        if (r0 < M) *reinterpret_cast<float2*>(out + (size_t)r0 * 64 + col)
                        = make_float2(acc[nt][0] + d0 * bb0, acc[nt][1] + d0 * bb1);
        if (r1 < M) *reinterpret_cast<float2*>(out + (size_t)r1 * 64 + col)
                        = make_float2(acc[nt][2] + d1 * bb0, acc[nt][3] + d1 * bb1);
    }
}

// ---------------- launch ----------------
extern "C" void kernel_launch(void* const* d_in, const int* in_sizes, int n_in,
                              void* d_out, int out_size) {
    const float* x  = (const float*)d_in[0];
    const int*   ei = (const int*)d_in[1];      // int32 (JAX x64 disabled)
    const float* ea = (const float*)d_in[2];
    const float* W1 = (const float*)d_in[3];
    const float* b1 = (const float*)d_in[4];
    const float* W2 = (const float*)d_in[5];
    const float* b2 = (const float*)d_in[6];
    float* out = (float*)d_out;

    int E = in_sizes[1] / 2;
    int M = out_size / 64;
    int mtiles = (M + 127) / 128;
    int etiles = (E + 127) / 128;

    cudaFuncSetAttribute(k2_kernel, cudaFuncAttributeMaxDynamicSharedMemorySize, K2_SMEM);

    int zn = M * 16 + M;
    zero_kernel<<<(zn + 255) / 256, 256>>>(M);
    k1_kernel<<<mtiles, 256>>>(x, W1, b1, M);
    k2_kernel<<<etiles, 256, K2_SMEM>>>(ei, ea, W1, E);
    k3_kernel<<<mtiles, 256>>>(W2, b2, out, M);
}

// round 9
// speedup vs baseline: 1.6861x; 1.0604x over previous
#include <cuda_runtime.h>
#include <cuda_fp16.h>
#include <cstdint>

#define NN 50000
#define NE 800000

// ---------------- device scratch ----------------
__device__ __half g_nmh[(size_t)NN * 128]; // fp16: [n][0:64]=x@W1a+b1, [n][64:128]=x@W1b
__device__ float  g_hsum[(size_t)NN * 64]; // fp32 per-node sum of relu(h)
__device__ float  g_deg[NN];               // per-node edge count

// ---------------- helpers ----------------
__device__ __forceinline__ uint32_t f2tf32(float f) {
    uint32_t r;
    asm("cvt.rna.tf32.f32 %0, %1;" : "=r"(r) : "f"(f));
    return r;
}
__device__ __forceinline__ void mma_tf32(float c[4],
                                         uint32_t a0, uint32_t a1, uint32_t a2, uint32_t a3,
                                         uint32_t b0, uint32_t b1) {
    asm volatile(
        "mma.sync.aligned.m16n8k8.row.col.f32.tf32.tf32.f32 "
        "{%0,%1,%2,%3}, {%4,%5,%6,%7}, {%8,%9}, {%0,%1,%2,%3};"
        : "+f"(c[0]), "+f"(c[1]), "+f"(c[2]), "+f"(c[3])
        : "r"(a0), "r"(a1), "r"(a2), "r"(a3), "r"(b0), "r"(b1));
}
__device__ __forceinline__ void red_add_v4(float* p, float a, float b, float c, float d) {
    asm volatile("red.global.add.v4.f32 [%0], {%1, %2, %3, %4};"
        :: "l"(p), "f"(a), "f"(b), "f"(c), "f"(d) : "memory");
}
__device__ __forceinline__ void red_add_f32(float* p, float v) {
    asm volatile("red.global.add.f32 [%0], %1;" :: "l"(p), "f"(v) : "memory");
}

// ================= K1: zero scratch + g_nmh = fp16(x @ [W1a|W1b] (+b1)) =================
__global__ __launch_bounds__(256)
void k1_kernel(const float* __restrict__ x, const float* __restrict__ W1,
               const float* __restrict__ b1, int M) {
    __shared__ uint32_t Ws[64 * 136];
    const int tid = threadIdx.x, lane = tid & 31, wid = tid >> 5;
    const int g = lane >> 2, tg = lane & 3;
    const int m0 = blockIdx.x * 128;

    // fused zero of g_hsum + g_deg (grid-stride)
    {
        const int gt = blockIdx.x * 256 + tid;
        const int nthr = gridDim.x * 256;
        const int h4 = M * 16;
        for (int i = gt; i < h4; i += nthr)
            reinterpret_cast<float4*>(g_hsum)[i] = make_float4(0.f, 0.f, 0.f, 0.f);
        for (int i = gt; i < M; i += nthr) g_deg[i] = 0.f;
    }

    for (int idx = tid; idx < 64 * 128; idx += 256) {
        int k = idx >> 7, n = idx & 127;
        float w = (n < 64) ? W1[k * 64 + n] : W1[(64 + k) * 64 + (n - 64)];
        Ws[k * 136 + n] = f2tf32(w);
    }
    __syncthreads();

    const int rb = wid * 16;
    const int r0 = m0 + rb + g, r1 = r0 + 8;
    const float* xr0 = x + (size_t)(r0 < M ? r0 : M - 1) * 64;
    const float* xr1 = x + (size_t)(r1 < M ? r1 : M - 1) * 64;

    uint32_t afr[8][4];
    #pragma unroll
    for (int kt = 0; kt < 8; kt++) {
        const int k0 = kt * 8;
        afr[kt][0] = f2tf32(__ldg(xr0 + k0 + tg));
        afr[kt][1] = f2tf32(__ldg(xr1 + k0 + tg));
        afr[kt][2] = f2tf32(__ldg(xr0 + k0 + tg + 4));
        afr[kt][3] = f2tf32(__ldg(xr1 + k0 + tg + 4));
    }

    float acc[16][4];
    #pragma unroll
    for (int nt = 0; nt < 16; nt++) acc[nt][0] = acc[nt][1] = acc[nt][2] = acc[nt][3] = 0.f;

    #pragma unroll
    for (int kt = 0; kt < 8; kt++) {
        const int k0 = kt * 8;
        #pragma unroll
        for (int nt = 0; nt < 16; nt++) {
            uint32_t b0 = Ws[(k0 + tg) * 136 + 8 * nt + g];
            uint32_t b1v = Ws[(k0 + tg + 4) * 136 + 8 * nt + g];
            mma_tf32(acc[nt], afr[kt][0], afr[kt][1], afr[kt][2], afr[kt][3], b0, b1v);
        }
    }
    #pragma unroll
    for (int nt = 0; nt < 16; nt++) {
        const int col = 8 * nt + 2 * tg;
        float e0 = 0.f, e1 = 0.f;
        if (col < 64) { e0 = __ldg(b1 + col); e1 = __ldg(b1 + col + 1); }
        if (r0 < M)
            *reinterpret_cast<__half2*>(g_nmh + (size_t)r0 * 128 + col)
                = __floats2half2_rn(acc[nt][0] + e0, acc[nt][1] + e1);
        if (r1 < M)
            *reinterpret_cast<__half2*>(g_nmh + (size_t)r1 * 128 + col)
                = __floats2half2_rn(acc[nt][2] + e0, acc[nt][3] + e1);
    }
}

// ================= K2: h = relu(pre[src]+post[dst]+ea@W1e) -> fp32 scatter =================
// smem words: Aea[128*20] | Wes[16*136] | Acc[128*68] | Ssrc[128] | Sdst[128]
#define AEA_O  0
#define WES_O  (128 * 20)
#define ACC_O  (WES_O + 16 * 136)
#define SSRC_O (ACC_O + 128 * 68)
#define SDST_O (SSRC_O + 128)
#define K2_SMEM ((SDST_O + 128) * 4)   // 54784 B
__global__ __launch_bounds__(256)
void k2_kernel(const int* __restrict__ ei, const float* __restrict__ ea,
               const float* __restrict__ W1, int E) {
    extern __shared__ float sm[];
    uint32_t* Aea = reinterpret_cast<uint32_t*>(sm) + AEA_O;
    uint32_t* Wes = reinterpret_cast<uint32_t*>(sm) + WES_O;
    float*    Acc = sm + ACC_O;
    int*      Ssrc = reinterpret_cast<int*>(sm) + SSRC_O;
    int*      Sdst = reinterpret_cast<int*>(sm) + SDST_O;

    const int tid = threadIdx.x, lane = tid & 31, wid = tid >> 5;
    const int g = lane >> 2, tg = lane & 3;
    const int e0 = blockIdx.x * 128;

    if (tid < 128) {
        int e = e0 + tid;
        Ssrc[tid] = (e < E) ? ei[e] : 0;
        Sdst[tid] = (e < E) ? ei[E + e] : 0;
    }
    #pragma unroll
    for (int p = 0; p < 2; p++) {
        int q = tid + 256 * p;            // 0..511
        int r = q >> 2, c = (q & 3) * 4;
        int e = e0 + r;
        float4 v = (e < E) ? __ldg(reinterpret_cast<const float4*>(ea + (size_t)e * 16 + c))
                           : make_float4(0.f, 0.f, 0.f, 0.f);
        uint4 u; u.x = f2tf32(v.x); u.y = f2tf32(v.y); u.z = f2tf32(v.z); u.w = f2tf32(v.w);
        *reinterpret_cast<uint4*>(Aea + r * 20 + c) = u;
    }
    for (int idx = tid; idx < 16 * 64; idx += 256) {
        int k = idx >> 6, n = idx & 63;
        Wes[k * 136 + n] = f2tf32(W1[(128 + k) * 64 + n]);
    }
    __syncthreads();

    // tiny MMA: acc = ea[128x16] @ W1e[16x64]
    const int rb = wid * 16;
    float acc[8][4];
    #pragma unroll
    for (int nt = 0; nt < 8; nt++) acc[nt][0] = acc[nt][1] = acc[nt][2] = acc[nt][3] = 0.f;
    #pragma unroll
    for (int kt = 0; kt < 2; kt++) {
        const int k0 = kt * 8;
        uint32_t a0 = Aea[(rb + g) * 20 + k0 + tg];
        uint32_t a1 = Aea[(rb + g + 8) * 20 + k0 + tg];
        uint32_t a2 = Aea[(rb + g) * 20 + k0 + tg + 4];
        uint32_t a3 = Aea[(rb + g + 8) * 20 + k0 + tg + 4];
        #pragma unroll
        for (int nt = 0; nt < 8; nt++) {
            uint32_t b0 = Wes[(k0 + tg) * 136 + 8 * nt + g];
            uint32_t b1v = Wes[(k0 + tg + 4) * 136 + 8 * nt + g];
            mma_tf32(acc[nt], a0, a1, a2, a3, b0, b1v);
        }
    }
    #pragma unroll
    for (int nt = 0; nt < 8; nt++) {
        const int col = 8 * nt + 2 * tg;
        *reinterpret_cast<float2*>(Acc + (rb + g) * 68 + col)     = make_float2(acc[nt][0], acc[nt][1]);
        *reinterpret_cast<float2*>(Acc + (rb + g + 8) * 68 + col) = make_float2(acc[nt][2], acc[nt][3]);
    }
    __syncthreads();

    // pass 2: batched fp16 gather (MLP=16) + relu + fp32 scatter
    const int rr = tid >> 4;              // 0..15
    const int c4 = (tid & 15) * 4;        // col quad

    int srcs[8], dsts[8];
    #pragma unroll
    for (int p = 0; p < 8; p++) {
        const int r = p * 16 + rr;
        srcs[p] = Ssrc[r];
        dsts[p] = Sdst[r];
    }
    uint2 preu[8], postu[8];
    #pragma unroll
    for (int p = 0; p < 8; p++)
        preu[p]  = __ldg(reinterpret_cast<const uint2*>(g_nmh + (size_t)srcs[p] * 128 + c4));
    #pragma unroll
    for (int p = 0; p < 8; p++)
        postu[p] = __ldg(reinterpret_cast<const uint2*>(g_nmh + (size_t)dsts[p] * 128 + 64 + c4));

    #pragma unroll
    for (int p = 0; p < 8; p++) {
        const int r = p * 16 + rr;
        if (e0 + r < E) {
            float2 pa = __half22float2(*reinterpret_cast<__half2*>(&preu[p].x));
            float2 pb = __half22float2(*reinterpret_cast<__half2*>(&preu[p].y));
            float2 qa = __half22float2(*reinterpret_cast<__half2*>(&postu[p].x));
            float2 qb = __half22float2(*reinterpret_cast<__half2*>(&postu[p].y));
            float4 a = *reinterpret_cast<const float4*>(Acc + r * 68 + c4);
            float hx = fmaxf(pa.x + qa.x + a.x, 0.f);
            float hy = fmaxf(pa.y + qa.y + a.y, 0.f);
            float hz = fmaxf(pb.x + qb.x + a.z, 0.f);
            float hw = fmaxf(pb.y + qb.y + a.w, 0.f);
            red_add_v4(g_hsum + (size_t)dsts[p] * 64 + c4, hx, hy, hz, hw);
            if ((tid & 15) == 0) red_add_f32(g_deg + dsts[p], 1.0f);
        }
    }
}

// ================= K3: out = g_hsum @ W2 + deg (x) b2 =================
__global__ __launch_bounds__(256)
void k3_kernel(const float* __restrict__ W2, const float* __restrict__ b2,
               float* __restrict__ out, int M) {
    __shared__ uint32_t Ws[64 * 72];
    const int tid = threadIdx.x, lane = tid & 31, wid = tid >> 5;
    const int g = lane >> 2, tg = lane & 3;
    const int m0 = blockIdx.x * 128;

    for (int idx = tid; idx < 64 * 64; idx += 256) {
        int k = idx >> 6, n = idx & 63;
        Ws[k * 72 + n] = f2tf32(W2[idx]);
    }
    __syncthreads();

    const int rb = wid * 16;
    const int r0 = m0 + rb + g, r1 = r0 + 8;
    const float* h0 = g_hsum + (size_t)(r0 < M ? r0 : M - 1) * 64;
    const float* h1 = g_hsum + (size_t)(r1 < M ? r1 : M - 1) * 64;

    uint32_t afr[8][4];
    #pragma unroll
    for (int kt = 0; kt < 8; kt++) {
        const int k0 = kt * 8;
        afr[kt][0] = f2tf32(__ldg(h0 + k0 + tg));
        afr[kt][1] = f2tf32(__ldg(h1 + k0 + tg));
        afr[kt][2] = f2tf32(__ldg(h0 + k0 + tg + 4));
        afr[kt][3] = f2tf32(__ldg(h1 + k0 + tg + 4));
    }

    float acc[8][4];
    #pragma unroll
    for (int nt = 0; nt < 8; nt++) acc[nt][0] = acc[nt][1] = acc[nt][2] = acc[nt][3] = 0.f;

    #pragma unroll
    for (int kt = 0; kt < 8; kt++) {
        const int k0 = kt * 8;
        #pragma unroll
        for (int nt = 0; nt < 8; nt++) {
            uint32_t b0 = Ws[(k0 + tg) * 72 + 8 * nt + g];
            uint32_t b1v = Ws[(k0 + tg + 4) * 72 + 8 * nt + g];
            mma_tf32(acc[nt], afr[kt][0], afr[kt][1], afr[kt][2], afr[kt][3], b0, b1v);
        }
    }
    const float d0 = (r0 < M) ? g_deg[r0] : 0.f;
    const float d1 = (r1 < M) ? g_deg[r1] : 0.f;
    #pragma unroll
    for (int nt = 0; nt < 8; nt++) {
        const int col = 8 * nt + 2 * tg;
        const float bb0 = __ldg(b2 + col), bb1 = __ldg(b2 + col + 1);
        if (r0 < M) *reinterpret_cast<float2*>(out + (size_t)r0 * 64 + col)
                        = make_float2(acc[nt][0] + d0 * bb0, acc[nt][1] + d0 * bb1);
        if (r1 < M) *reinterpret_cast<float2*>(out + (size_t)r1 * 64 + col)
                        = make_float2(acc[nt][2] + d1 * bb0, acc[nt][3] + d1 * bb1);
    }
}

// ---------------- launch ----------------
extern "C" void kernel_launch(void* const* d_in, const int* in_sizes, int n_in,
                              void* d_out, int out_size) {
    const float* x  = (const float*)d_in[0];
    const int*   ei = (const int*)d_in[1];      // int32 (JAX x64 disabled)
    const float* ea = (const float*)d_in[2];
    const float* W1 = (const float*)d_in[3];
    const float* b1 = (const float*)d_in[4];
    const float* W2 = (const float*)d_in[5];
    const float* b2 = (const float*)d_in[6];
    float* out = (float*)d_out;

    int E = in_sizes[1] / 2;
    int M = out_size / 64;
    int mtiles = (M + 127) / 128;
    int etiles = (E + 127) / 128;

    cudaFuncSetAttribute(k2_kernel, cudaFuncAttributeMaxDynamicSharedMemorySize, K2_SMEM);

    k1_kernel<<<mtiles, 256>>>(x, W1, b1, M);
    k2_kernel<<<etiles, 256, K2_SMEM>>>(ei, ea, W1, E);
    k3_kernel<<<mtiles, 256>>>(W2, b2, out, M);
}

// round 10
// speedup vs baseline: 1.8036x; 1.0696x over previous
#include <cuda_runtime.h>
#include <cuda_fp16.h>
#include <cstdint>

#define NN 50000
#define NE 800000

// ---------------- device scratch (zero-initialized at load; K3 restores zeros) ----------------
__device__ __half g_nmh[(size_t)NN * 128]; // fp16: [n][0:64]=x@W1a+b1, [n][64:128]=x@W1b
__device__ float  g_hsum[(size_t)NN * 64]; // fp32 per-node sum of relu(h)
__device__ float  g_deg[NN];               // per-node edge count

// ---------------- helpers ----------------
__device__ __forceinline__ uint32_t f2tf32(float f) {
    uint32_t r;
    asm("cvt.rna.tf32.f32 %0, %1;" : "=r"(r) : "f"(f));
    return r;
}
__device__ __forceinline__ void mma_tf32(float c[4],
                                         uint32_t a0, uint32_t a1, uint32_t a2, uint32_t a3,
                                         uint32_t b0, uint32_t b1) {
    asm volatile(
        "mma.sync.aligned.m16n8k8.row.col.f32.tf32.tf32.f32 "
        "{%0,%1,%2,%3}, {%4,%5,%6,%7}, {%8,%9}, {%0,%1,%2,%3};"
        : "+f"(c[0]), "+f"(c[1]), "+f"(c[2]), "+f"(c[3])
        : "r"(a0), "r"(a1), "r"(a2), "r"(a3), "r"(b0), "r"(b1));
}
__device__ __forceinline__ void red_add_v4(float* p, float a, float b, float c, float d) {
    asm volatile("red.global.add.v4.f32 [%0], {%1, %2, %3, %4};"
        :: "l"(p), "f"(a), "f"(b), "f"(c), "f"(d) : "memory");
}
__device__ __forceinline__ void red_add_f32(float* p, float v) {
    asm volatile("red.global.add.f32 [%0], %1;" :: "l"(p), "f"(v) : "memory");
}

// ================= K1: deg histogram + g_nmh = fp16(x @ [W1a|W1b] (+b1)) =================
__global__ __launch_bounds__(256, 3)
void k1_kernel(const float* __restrict__ x, const int* __restrict__ ei,
               const float* __restrict__ W1, const float* __restrict__ b1,
               int E, int M) {
    __shared__ uint32_t Ws[64 * 136];
    const int tid = threadIdx.x, lane = tid & 31, wid = tid >> 5;
    const int g = lane >> 2, tg = lane & 3;
    const int m0 = blockIdx.x * 128;

    for (int idx = tid; idx < 64 * 128; idx += 256) {
        int k = idx >> 7, n = idx & 127;
        float w = (n < 64) ? W1[k * 64 + n] : W1[(64 + k) * 64 + (n - 64)];
        Ws[k * 136 + n] = f2tf32(w);
    }
    // deg histogram (g_deg zeroed by previous K3 / initial zero-init)
    {
        const int gt = blockIdx.x * 256 + tid;
        const int nthr = gridDim.x * 256;
        for (int i = gt; i < E; i += nthr)
            red_add_f32(&g_deg[__ldg(ei + E + i)], 1.0f);
    }
    __syncthreads();

    const int rb = wid * 16;
    const int r0 = m0 + rb + g, r1 = r0 + 8;
    const float* xr0 = x + (size_t)(r0 < M ? r0 : M - 1) * 64;
    const float* xr1 = x + (size_t)(r1 < M ? r1 : M - 1) * 64;

    uint32_t afr[8][4];
    #pragma unroll
    for (int kt = 0; kt < 8; kt++) {
        const int k0 = kt * 8;
        afr[kt][0] = f2tf32(__ldg(xr0 + k0 + tg));
        afr[kt][1] = f2tf32(__ldg(xr1 + k0 + tg));
        afr[kt][2] = f2tf32(__ldg(xr0 + k0 + tg + 4));
        afr[kt][3] = f2tf32(__ldg(xr1 + k0 + tg + 4));
    }

    #pragma unroll
    for (int half = 0; half < 2; half++) {
        float acc[8][4];
        #pragma unroll
        for (int nt = 0; nt < 8; nt++)
            acc[nt][0] = acc[nt][1] = acc[nt][2] = acc[nt][3] = 0.f;

        #pragma unroll
        for (int kt = 0; kt < 8; kt++) {
            const int k0 = kt * 8;
            #pragma unroll
            for (int nt = 0; nt < 8; nt++) {
                uint32_t b0 = Ws[(k0 + tg) * 136 + half * 64 + 8 * nt + g];
                uint32_t b1v = Ws[(k0 + tg + 4) * 136 + half * 64 + 8 * nt + g];
                mma_tf32(acc[nt], afr[kt][0], afr[kt][1], afr[kt][2], afr[kt][3], b0, b1v);
            }
        }
        #pragma unroll
        for (int nt = 0; nt < 8; nt++) {
            const int col = half * 64 + 8 * nt + 2 * tg;
            float e0 = 0.f, e1 = 0.f;
            if (half == 0) { e0 = __ldg(b1 + col); e1 = __ldg(b1 + col + 1); }
            if (r0 < M)
                *reinterpret_cast<__half2*>(g_nmh + (size_t)r0 * 128 + col)
                    = __floats2half2_rn(acc[nt][0] + e0, acc[nt][1] + e1);
            if (r1 < M)
                *reinterpret_cast<__half2*>(g_nmh + (size_t)r1 * 128 + col)
                    = __floats2half2_rn(acc[nt][2] + e0, acc[nt][3] + e1);
        }
    }
}

// ================= K2: h = relu(pre[src]+post[dst]+ea@W1e) -> fp32 scatter =================
// smem words: Aea[128*20] | Wes[16*136] | AccH[128*72 halves = 4608 w] | Ssrc[128] | Sdst[128]
#define AEA_O  0
#define WES_O  (128 * 20)
#define ACCH_O (WES_O + 16 * 136)
#define SSRC_O (ACCH_O + 4608)
#define SDST_O (SSRC_O + 128)
#define K2_SMEM ((SDST_O + 128) * 4)   // 38400 B
__global__ __launch_bounds__(256, 4)
void k2_kernel(const int* __restrict__ ei, const float* __restrict__ ea,
               const float* __restrict__ W1, int E) {
    extern __shared__ float sm[];
    uint32_t* Aea = reinterpret_cast<uint32_t*>(sm) + AEA_O;
    uint32_t* Wes = reinterpret_cast<uint32_t*>(sm) + WES_O;
    __half*   AccH = reinterpret_cast<__half*>(sm + ACCH_O);
    int*      Ssrc = reinterpret_cast<int*>(sm) + SSRC_O;
    int*      Sdst = reinterpret_cast<int*>(sm) + SDST_O;

    const int tid = threadIdx.x, lane = tid & 31, wid = tid >> 5;
    const int g = lane >> 2, tg = lane & 3;
    const int e0 = blockIdx.x * 128;

    if (tid < 128) {
        int e = e0 + tid;
        Ssrc[tid] = (e < E) ? ei[e] : 0;
        Sdst[tid] = (e < E) ? ei[E + e] : 0;
    }
    #pragma unroll
    for (int p = 0; p < 2; p++) {
        int q = tid + 256 * p;            // 0..511
        int r = q >> 2, c = (q & 3) * 4;
        int e = e0 + r;
        float4 v = (e < E) ? __ldg(reinterpret_cast<const float4*>(ea + (size_t)e * 16 + c))
                           : make_float4(0.f, 0.f, 0.f, 0.f);
        uint4 u; u.x = f2tf32(v.x); u.y = f2tf32(v.y); u.z = f2tf32(v.z); u.w = f2tf32(v.w);
        *reinterpret_cast<uint4*>(Aea + r * 20 + c) = u;
    }
    for (int idx = tid; idx < 16 * 64; idx += 256) {
        int k = idx >> 6, n = idx & 63;
        Wes[k * 136 + n] = f2tf32(W1[(128 + k) * 64 + n]);
    }
    __syncthreads();

    // tiny MMA: acc = ea[128x16] @ W1e[16x64], stored fp16
    const int rb = wid * 16;
    float acc[8][4];
    #pragma unroll
    for (int nt = 0; nt < 8; nt++) acc[nt][0] = acc[nt][1] = acc[nt][2] = acc[nt][3] = 0.f;
    #pragma unroll
    for (int kt = 0; kt < 2; kt++) {
        const int k0 = kt * 8;
        uint32_t a0 = Aea[(rb + g) * 20 + k0 + tg];
        uint32_t a1 = Aea[(rb + g + 8) * 20 + k0 + tg];
        uint32_t a2 = Aea[(rb + g) * 20 + k0 + tg + 4];
        uint32_t a3 = Aea[(rb + g + 8) * 20 + k0 + tg + 4];
        #pragma unroll
        for (int nt = 0; nt < 8; nt++) {
            uint32_t b0 = Wes[(k0 + tg) * 136 + 8 * nt + g];
            uint32_t b1v = Wes[(k0 + tg + 4) * 136 + 8 * nt + g];
            mma_tf32(acc[nt], a0, a1, a2, a3, b0, b1v);
        }
    }
    #pragma unroll
    for (int nt = 0; nt < 8; nt++) {
        const int col = 8 * nt + 2 * tg;
        *reinterpret_cast<__half2*>(AccH + (rb + g) * 72 + col)
            = __floats2half2_rn(acc[nt][0], acc[nt][1]);
        *reinterpret_cast<__half2*>(AccH + (rb + g + 8) * 72 + col)
            = __floats2half2_rn(acc[nt][2], acc[nt][3]);
    }
    __syncthreads();

    // pass 2: batched fp16 gather (MLP=16) + relu + fp32 scatter
    const int rr = tid >> 4;              // 0..15
    const int c4 = (tid & 15) * 4;        // col quad

    int srcs[8], dsts[8];
    #pragma unroll
    for (int p = 0; p < 8; p++) {
        const int r = p * 16 + rr;
        srcs[p] = Ssrc[r];
        dsts[p] = Sdst[r];
    }
    uint2 preu[8], postu[8];
    #pragma unroll
    for (int p = 0; p < 8; p++)
        preu[p]  = __ldg(reinterpret_cast<const uint2*>(g_nmh + (size_t)srcs[p] * 128 + c4));
    #pragma unroll
    for (int p = 0; p < 8; p++)
        postu[p] = __ldg(reinterpret_cast<const uint2*>(g_nmh + (size_t)dsts[p] * 128 + 64 + c4));

    #pragma unroll
    for (int p = 0; p < 8; p++) {
        const int r = p * 16 + rr;
        if (e0 + r < E) {
            float2 pa = __half22float2(*reinterpret_cast<__half2*>(&preu[p].x));
            float2 pb = __half22float2(*reinterpret_cast<__half2*>(&preu[p].y));
            float2 qa = __half22float2(*reinterpret_cast<__half2*>(&postu[p].x));
            float2 qb = __half22float2(*reinterpret_cast<__half2*>(&postu[p].y));
            uint2 au = *reinterpret_cast<const uint2*>(AccH + r * 72 + c4);
            float2 a01 = __half22float2(*reinterpret_cast<__half2*>(&au.x));
            float2 a23 = __half22float2(*reinterpret_cast<__half2*>(&au.y));
            float hx = fmaxf(pa.x + qa.x + a01.x, 0.f);
            float hy = fmaxf(pa.y + qa.y + a01.y, 0.f);
            float hz = fmaxf(pb.x + qb.x + a23.x, 0.f);
            float hw = fmaxf(pb.y + qb.y + a23.y, 0.f);
            red_add_v4(g_hsum + (size_t)dsts[p] * 64 + c4, hx, hy, hz, hw);
        }
    }
}

// ================= K3: out = g_hsum @ W2 + deg (x) b2; re-zero consumed state =================
__global__ __launch_bounds__(256, 4)
void k3_kernel(const float* __restrict__ W2, const float* __restrict__ b2,
               float* __restrict__ out, int M) {
    __shared__ uint32_t Ws[64 * 72];
    const int tid = threadIdx.x, lane = tid & 31, wid = tid >> 5;
    const int g = lane >> 2, tg = lane & 3;
    const int m0 = blockIdx.x * 128;

    for (int idx = tid; idx < 64 * 64; idx += 256) {
        int k = idx >> 6, n = idx & 63;
        Ws[k * 72 + n] = f2tf32(W2[idx]);
    }
    __syncthreads();

    const int rb = wid * 16;
    const int r0 = m0 + rb + g, r1 = r0 + 8;
    float* h0 = g_hsum + (size_t)(r0 < M ? r0 : M - 1) * 64;
    float* h1 = g_hsum + (size_t)(r1 < M ? r1 : M - 1) * 64;

    uint32_t afr[8][4];
    #pragma unroll
    for (int kt = 0; kt < 8; kt++) {
        const int k0 = kt * 8;
        afr[kt][0] = f2tf32(__ldg(h0 + k0 + tg));
        afr[kt][1] = f2tf32(__ldg(h1 + k0 + tg));
        afr[kt][2] = f2tf32(__ldg(h0 + k0 + tg + 4));
        afr[kt][3] = f2tf32(__ldg(h1 + k0 + tg + 4));
    }
    const float d0 = (r0 < M) ? g_deg[r0] : 0.f;
    const float d1 = (r1 < M) ? g_deg[r1] : 0.f;
    __syncwarp();   // all reads of this warp's rows done before any lane re-zeroes

    // re-zero consumed state for the next graph replay (rows are warp-exclusive;
    // each thread zeroes exactly the addresses it loaded)
    #pragma unroll
    for (int kt = 0; kt < 8; kt++) {
        const int k0 = kt * 8;
        if (r0 < M) { h0[k0 + tg] = 0.f; h0[k0 + tg + 4] = 0.f; }
        if (r1 < M) { h1[k0 + tg] = 0.f; h1[k0 + tg + 4] = 0.f; }
    }
    if (tg == 0) {
        if (r0 < M) g_deg[r0] = 0.f;
        if (r1 < M) g_deg[r1] = 0.f;
    }

    float acc[8][4];
    #pragma unroll
    for (int nt = 0; nt < 8; nt++) acc[nt][0] = acc[nt][1] = acc[nt][2] = acc[nt][3] = 0.f;

    #pragma unroll
    for (int kt = 0; kt < 8; kt++) {
        const int k0 = kt * 8;
        #pragma unroll
        for (int nt = 0; nt < 8; nt++) {
            uint32_t b0 = Ws[(k0 + tg) * 72 + 8 * nt + g];
            uint32_t b1v = Ws[(k0 + tg + 4) * 72 + 8 * nt + g];
            mma_tf32(acc[nt], afr[kt][0], afr[kt][1], afr[kt][2], afr[kt][3], b0, b1v);
        }
    }
    #pragma unroll
    for (int nt = 0; nt < 8; nt++) {
        const int col = 8 * nt + 2 * tg;
        const float bb0 = __ldg(b2 + col), bb1 = __ldg(b2 + col + 1);
        if (r0 < M) *reinterpret_cast<float2*>(out + (size_t)r0 * 64 + col)
                        = make_float2(acc[nt][0] + d0 * bb0, acc[nt][1] + d0 * bb1);
        if (r1 < M) *reinterpret_cast<float2*>(out + (size_t)r1 * 64 + col)
                        = make_float2(acc[nt][2] + d1 * bb0, acc[nt][3] + d1 * bb1);
    }
}

// ---------------- launch ----------------
extern "C" void kernel_launch(void* const* d_in, const int* in_sizes, int n_in,
                              void* d_out, int out_size) {
    const float* x  = (const float*)d_in[0];
    const int*   ei = (const int*)d_in[1];      // int32 (JAX x64 disabled)
    const float* ea = (const float*)d_in[2];
    const float* W1 = (const float*)d_in[3];
    const float* b1 = (const float*)d_in[4];
    const float* W2 = (const float*)d_in[5];
    const float* b2 = (const float*)d_in[6];
    float* out = (float*)d_out;

    int E = in_sizes[1] / 2;
    int M = out_size / 64;
    int mtiles = (M + 127) / 128;
    int etiles = (E + 127) / 128;

    cudaFuncSetAttribute(k2_kernel, cudaFuncAttributeMaxDynamicSharedMemorySize, K2_SMEM);

    k1_kernel<<<mtiles, 256>>>(x, ei, W1, b1, E, M);
    k2_kernel<<<etiles, 256, K2_SMEM>>>(ei, ea, W1, E);
    k3_kernel<<<mtiles, 256>>>(W2, b2, out, M);
}